// round 1
// baseline (speedup 1.0000x reference)
#include <cuda_runtime.h>
#include <math_constants.h>

#define D_DIM 64
#define K_CODES 2048
#define NVEC 131072                 // 16*1024*8 vectors
#define BM 64
#define BN 64
#define CODES_ELEMS (NVEC * D_DIM)  // 8388608
#define NBLOCKS (NVEC / BM)         // 2048

__device__ float g_cnorm[K_CODES];
__device__ float g_partials[NBLOCKS];

// ---------------------------------------------------------------------------
// Kernel 1: codebook squared norms
// ---------------------------------------------------------------------------
__global__ void cnorm_kernel(const float* __restrict__ cb) {
    int k = blockIdx.x * blockDim.x + threadIdx.x;
    if (k < K_CODES) {
        const float4* row = (const float4*)(cb + (size_t)k * D_DIM);
        float s = 0.f;
#pragma unroll
        for (int i = 0; i < D_DIM / 4; i++) {
            float4 v = row[i];
            s += v.x * v.x + v.y * v.y + v.z * v.z + v.w * v.w;
        }
        g_cnorm[k] = s;
    }
}

// ---------------------------------------------------------------------------
// Kernel 2: distance GEMM + argmin + gather + commit partial
// ---------------------------------------------------------------------------
__global__ __launch_bounds__(256) void vq_kernel(const float* __restrict__ z,
                                                 const float* __restrict__ cb,
                                                 float* __restrict__ out) {
    __shared__ float zs[D_DIM][BM];   // K-major z tile   [k][row]
    __shared__ float cs[D_DIM][BN];   // K-major code tile [k][col]
    __shared__ float cn[BN];
    __shared__ int sidx[BM];
    __shared__ float red[256];

    const int tid = threadIdx.x;
    const int m0 = blockIdx.x * BM;

    // Load z tile (64 rows x 64 d), transposed into smem. 1024 float4 total.
#pragma unroll
    for (int it = 0; it < 4; it++) {
        int e = tid + it * 256;          // 0..1023
        int row = e >> 4;                // 0..63
        int dq = e & 15;                 // float4 index along d
        float4 v = *(const float4*)(z + (size_t)(m0 + row) * D_DIM + dq * 4);
        zs[dq * 4 + 0][row] = v.x;
        zs[dq * 4 + 1][row] = v.y;
        zs[dq * 4 + 2][row] = v.z;
        zs[dq * 4 + 3][row] = v.w;
    }

    const int trow = tid >> 4;   // 0..15 -> rows trow*4 .. trow*4+3
    const int tcol = tid & 15;   // 0..15 -> cols tcol*4 .. tcol*4+3

    float bestv[4];
    int besti[4];
#pragma unroll
    for (int i = 0; i < 4; i++) { bestv[i] = CUDART_INF_F; besti[i] = 0; }

    for (int k0 = 0; k0 < K_CODES; k0 += BN) {
        __syncthreads();  // protect cs from previous iteration's readers
#pragma unroll
        for (int it = 0; it < 4; it++) {
            int e = tid + it * 256;
            int col = e >> 4;
            int dq = e & 15;
            float4 v = *(const float4*)(cb + (size_t)(k0 + col) * D_DIM + dq * 4);
            cs[dq * 4 + 0][col] = v.x;
            cs[dq * 4 + 1][col] = v.y;
            cs[dq * 4 + 2][col] = v.z;
            cs[dq * 4 + 3][col] = v.w;
        }
        if (tid < BN) cn[tid] = g_cnorm[k0 + tid];
        __syncthreads();

        float acc[4][4];
#pragma unroll
        for (int i = 0; i < 4; i++)
#pragma unroll
            for (int j = 0; j < 4; j++) acc[i][j] = 0.f;

#pragma unroll
        for (int k = 0; k < D_DIM; k++) {
            float4 a = *(const float4*)&zs[k][trow * 4];
            float4 b = *(const float4*)&cs[k][tcol * 4];
            float av[4] = {a.x, a.y, a.z, a.w};
            float bv[4] = {b.x, b.y, b.z, b.w};
#pragma unroll
            for (int i = 0; i < 4; i++)
#pragma unroll
                for (int j = 0; j < 4; j++) acc[i][j] += av[i] * bv[j];
        }

        // dist = ||c||^2 - 2*dot  (row-constant ||z||^2 dropped for argmin)
#pragma unroll
        for (int j = 0; j < 4; j++) {
            float c = cn[tcol * 4 + j];
            int kidx = k0 + tcol * 4 + j;
#pragma unroll
            for (int i = 0; i < 4; i++) {
                float v = fmaf(-2.f, acc[i][j], c);
                if (v < bestv[i]) { bestv[i] = v; besti[i] = kidx; }
            }
        }
    }

    // Reduce across the 16 threads sharing each row group (width-16 segments)
#pragma unroll
    for (int off = 8; off >= 1; off >>= 1) {
#pragma unroll
        for (int i = 0; i < 4; i++) {
            float ov = __shfl_down_sync(0xffffffffu, bestv[i], off, 16);
            int oi = __shfl_down_sync(0xffffffffu, besti[i], off, 16);
            if (ov < bestv[i] || (ov == bestv[i] && oi < besti[i])) {
                bestv[i] = ov;
                besti[i] = oi;
            }
        }
    }
    if (tcol == 0) {
#pragma unroll
        for (int i = 0; i < 4; i++) sidx[trow * 4 + i] = besti[i];
    }
    __syncthreads();

    // Epilogue: gather codebook rows (codes), write indices, commit partial
    float lsum = 0.f;
#pragma unroll
    for (int it = 0; it < 16; it++) {
        int e = tid + it * 256;   // 0..4095
        int row = e >> 6;
        int d = e & 63;
        int ci = sidx[row];
        float cv = __ldg(cb + (size_t)ci * D_DIM + d);
        float zv = zs[d][row];
        float diff = cv - zv;
        lsum += diff * diff;
        out[(size_t)(m0 + row) * D_DIM + d] = cv;
    }
    if (tid < BM) out[CODES_ELEMS + m0 + tid] = (float)sidx[tid];

    red[tid] = lsum;
    __syncthreads();
#pragma unroll
    for (int s = 128; s > 0; s >>= 1) {
        if (tid < s) red[tid] += red[tid + s];
        __syncthreads();
    }
    if (tid == 0) g_partials[blockIdx.x] = red[0];
}

// ---------------------------------------------------------------------------
// Kernel 3: deterministic commit-loss reduction (fixed order, double accum)
// ---------------------------------------------------------------------------
__global__ void final_kernel(float* __restrict__ out) {
    __shared__ double dred[256];
    int tid = threadIdx.x;
    double s = 0.0;
    for (int i = tid; i < NBLOCKS; i += 256) s += (double)g_partials[i];
    dred[tid] = s;
    __syncthreads();
#pragma unroll
    for (int st = 128; st > 0; st >>= 1) {
        if (tid < st) dred[tid] += dred[tid + st];
        __syncthreads();
    }
    if (tid == 0)
        out[CODES_ELEMS + NVEC] = (float)(dred[0] / (double)CODES_ELEMS);
}

// ---------------------------------------------------------------------------
extern "C" void kernel_launch(void* const* d_in, const int* in_sizes, int n_in,
                              void* d_out, int out_size) {
    const float* z = (const float*)d_in[0];
    const float* cb = (const float*)d_in[1];
    // Robustness: z has 8.4M elements, codebook 131072
    if (n_in >= 2 && in_sizes[0] < in_sizes[1]) {
        const float* t = z; z = cb; cb = t;
    }
    float* out = (float*)d_out;

    cnorm_kernel<<<(K_CODES + 255) / 256, 256>>>(cb);
    vq_kernel<<<NBLOCKS, 256>>>(z, cb, out);
    final_kernel<<<1, 256>>>(out);
}